// round 12
// baseline (speedup 1.0000x reference)
#include <cuda_runtime.h>
#include <math_constants.h>

#define NB 4
#define NN 16384
#define NM 512
#define NC 128
#define NK 16
#define NL 6
#define NSTEPS 5

// ---------------- scratch (device globals: no allocations allowed) ----------
__device__ float g_feats[NB*NN*NC];
__device__ float g_Qf[NB*NN*NC];
__device__ float g_Gf[NB*NN*NC];
__device__ __align__(16) float g_pos4[NB*NN*4];
__device__ float g_wsel[NB*NM*NL*NC];
__device__ float g_rout[2][NB*NM*NL*NC];
__device__ float g_disp[NB*NM*3];

// ---------------- f32x2 packed helpers --------------------------------------
__device__ __forceinline__ void dfma2(unsigned long long& d,
                                      unsigned long long a,
                                      unsigned long long b) {
    asm("fma.rn.f32x2 %0, %1, %2, %0;" : "+l"(d) : "l"(a), "l"(b));
}
__device__ __forceinline__ unsigned long long dadd2(unsigned long long a,
                                                    unsigned long long b) {
    unsigned long long r;
    asm("add.rn.f32x2 %0, %1, %2;" : "=l"(r) : "l"(a), "l"(b));
    return r;
}
__device__ __forceinline__ unsigned long long dmul2(unsigned long long a,
                                                    unsigned long long b) {
    unsigned long long r;
    asm("mul.rn.f32x2 %0, %1, %2;" : "=l"(r) : "l"(a), "l"(b));
    return r;
}
__device__ __forceinline__ unsigned long long dfmar2(unsigned long long a,
                                                     unsigned long long b,
                                                     unsigned long long c) {
    unsigned long long r;
    asm("fma.rn.f32x2 %0, %1, %2, %3;" : "=l"(r) : "l"(a), "l"(b), "l"(c));
    return r;
}
__device__ __forceinline__ unsigned long long packdup(float w) {
    unsigned long long r;
    asm("mov.b64 %0, {%1, %1};" : "=l"(r) : "f"(w));
    return r;
}
__device__ __forceinline__ void unpack2(unsigned long long a, float& lo, float& hi) {
    asm("mov.b64 {%0, %1}, %2;" : "=f"(lo), "=f"(hi) : "l"(a));
}

// ---------------- init: padded positions -------------------------------------
__global__ void init_pos_kernel(const float* __restrict__ xyz) {
    int i = blockIdx.x * blockDim.x + threadIdx.x;
    if (i < NB*NN) {
        float x = xyz[i*3+0], y = xyz[i*3+1], z = xyz[i*3+2];
        *(float4*)&g_pos4[(size_t)i*4] = make_float4(x, y, z, 0.f);
    }
}

// ---------------- encoder ---------------------------------------------------
__global__ void encode_kernel(const float* __restrict__ xyz,
                              const float* __restrict__ w1, const float* __restrict__ b1,
                              const float* __restrict__ w2, const float* __restrict__ b2) {
    __shared__ float h[4][64];
    int tid = threadIdx.x;
    int p0 = blockIdx.x * 4;
    for (int i = tid; i < 4*64; i += 128) {
        int pt = i >> 6, j = i & 63;
        const float* x = xyz + (size_t)(p0 + pt) * 3;
        float v = b1[j] + w1[j*3+0]*x[0] + w1[j*3+1]*x[1] + w1[j*3+2]*x[2];
        h[pt][j] = fmaxf(v, 0.f);
    }
    __syncthreads();
    float acc[4];
    #pragma unroll
    for (int p = 0; p < 4; p++) acc[p] = b2[tid];
    const float4* wr = (const float4*)(w2 + (size_t)tid * 64);
    #pragma unroll
    for (int j4 = 0; j4 < 16; j4++) {
        float4 w = wr[j4];
        #pragma unroll
        for (int p = 0; p < 4; p++) {
            float4 hv = *(const float4*)&h[p][4*j4];
            acc[p] += w.x*hv.x + w.y*hv.y + w.z*hv.z + w.w*hv.w;
        }
    }
    #pragma unroll
    for (int p = 0; p < 4; p++)
        g_feats[(size_t)(p0 + p) * NC + tid] = acc[p];
}

// ---------------- beta/gamma projections (f32x2 point-pairs) ----------------
__global__ void proj_kernel(const float* __restrict__ bw, const float* __restrict__ bb,
                            const float* __restrict__ gw, const float* __restrict__ gb) {
    __shared__ __align__(8) float xs[128*16];      // xs[ch*16 + p]
    int c = threadIdx.x;                           // 128 threads
    size_t base = (size_t)blockIdx.x * 16 * 128;
    for (int i = c; i < 16*128; i += 128) {
        int p = i >> 7, ch = i & 127;
        xs[ch*16 + p] = g_feats[base + i];
    }
    __syncthreads();
    unsigned long long accQ[8], accG[8];
    unsigned long long bq = packdup(bb[c]), bg = packdup(gb[c]);
    #pragma unroll
    for (int p = 0; p < 8; p++) { accQ[p] = bq; accG[p] = bg; }
    const float4* wq = (const float4*)(bw + (size_t)c * 128);
    const float4* wg = (const float4*)(gw + (size_t)c * 128);
    for (int j4 = 0; j4 < 32; j4++) {
        float4 a = wq[j4];
        float4 g = wg[j4];
        float aa[4] = {a.x, a.y, a.z, a.w};
        float gg2[4] = {g.x, g.y, g.z, g.w};
        #pragma unroll
        for (int jj = 0; jj < 4; jj++) {
            int ch = 4*j4 + jj;
            unsigned long long wa = packdup(aa[jj]);
            unsigned long long wgv = packdup(gg2[jj]);
            const unsigned long long* x2 = (const unsigned long long*)&xs[ch*16];
            #pragma unroll
            for (int p = 0; p < 8; p++) {
                dfma2(accQ[p], x2[p], wa);
                dfma2(accG[p], x2[p], wgv);
            }
        }
    }
    #pragma unroll
    for (int p = 0; p < 8; p++) {
        float q0, q1, g0, g1;
        unpack2(accQ[p], q0, q1);
        unpack2(accG[p], g0, g1);
        g_Qf[base + (size_t)(2*p)*128 + c]   = q0;
        g_Qf[base + (size_t)(2*p+1)*128 + c] = q1;
        g_Gf[base + (size_t)(2*p)*128 + c]   = g0;
        g_Gf[base + (size_t)(2*p+1)*128 + c] = g1;
    }
}

// ---------------- KNN: warp-distributed sorted top-17 insert ----------------
// Inserting a candidate whose (d, idx) key ranks >= 17 is a no-op (its
// position pn >= 17, so no lane < 17 matches lane==pn or lane>pn<17).
__device__ __forceinline__ void insert_one(float dc, int ic,
                                           float& ld, int& li, int lane) {
    float pd = __shfl_up_sync(0xffffffffu, ld, 1);
    int   pi = __shfl_up_sync(0xffffffffu, li, 1);
    unsigned lt = __ballot_sync(0xffffffffu,
            (ld < dc) || ((ld == dc) && (li < ic))) & 0x1FFFFu;
    int pn = __popc(lt);
    if (lane < 17) {
        if (lane == pn)      { ld = dc; li = ic; }
        else if (lane > pn)  { ld = pd; li = pi; }
    }
}

__device__ __forceinline__ void insert2(unsigned bal, float d0, float d1, int c0,
                                        float& ld, int& li, float& tau, int lane) {
    do {
        int src = __ffs(bal) - 1; bal &= bal - 1;
        float e0 = __shfl_sync(0xffffffffu, d0, src);
        float e1 = __shfl_sync(0xffffffffu, d1, src);
        int   ci = __shfl_sync(0xffffffffu, c0, src);
        insert_one(e0, ci,     ld, li, lane);
        insert_one(e1, ci + 1, ld, li, lane);
    } while (bal);
    tau = __shfl_sync(0xffffffffu, ld, 16);
}

// ---------------- fused per-step selector ------------------------------------
// 512 blocks x 512 threads. 4 queries/block; each query scanned by FOUR warps
// (quarter-scans of the candidate set), exact 4-way merge of sorted top-17
// lists, then logits + gumbel argmax by the primary warp. Tiles staged in SoA
// smem, 2 candidates per lane per iteration via packed f32x2, ONE ballot per
// candidate pair.
#define KTPB 512
#define KQB 4
#define KTILE 2048

__global__ __launch_bounds__(KTPB)
void knn_step_kernel(const int* __restrict__ start,
                     const float* __restrict__ gumbel, int t) {
    __shared__ __align__(8) float sx[KTILE], sy[KTILE], sz[KTILE];
    __shared__ unsigned long long mkeys[KQB][4][17];
    __shared__ int sknn[KQB][NK];
    __shared__ int snext[KQB];
    int tid = threadIdx.x, warp = tid >> 5, lane = tid & 31;
    int q = warp & 3, quarter = warp >> 2;
    int b = blockIdx.x / (NM/KQB);
    int m = (blockIdx.x % (NM/KQB)) * KQB + q;
    int gw = b*NM + m;
    int qidx = start[gw];
    const float4* pos = (const float4*)(g_pos4 + (size_t)b*NN*4);
    const float* Gf = g_Gf + (size_t)b*NN*NC;

    if (quarter == 0) {   // walk[0] = feats[start]
        const float* fr = g_feats + ((size_t)b*NN + qidx) * NC;
        float* wr = g_wsel + (size_t)gw * NL * NC;
        #pragma unroll
        for (int r = 0; r < 4; r++) wr[lane + 32*r] = fr[lane + 32*r];
    }

    for (int l = 0; l < NL-1; l++) {
        float4 qp = pos[qidx];
        unsigned long long nqx = packdup(-qp.x);
        unsigned long long nqy = packdup(-qp.y);
        unsigned long long nqz = packdup(-qp.z);
        float ld = CUDART_INF_F;
        int   li = 0x7FFFFFFF;
        float tau = CUDART_INF_F;

        for (int tb = 0; tb < NN/KTILE; tb++) {
            __syncthreads();
            const float4* srcp = pos + tb*KTILE;
            for (int i = tid; i < KTILE; i += KTPB) {
                float4 p = srcp[i];
                sx[i] = p.x; sy[i] = p.y; sz[i] = p.z;
            }
            __syncthreads();
            const unsigned long long* sx2 = (const unsigned long long*)sx;
            const unsigned long long* sy2 = (const unsigned long long*)sy;
            const unsigned long long* sz2 = (const unsigned long long*)sz;
            int base = tb * KTILE;
            for (int pi = quarter*32 + lane; pi < KTILE/2; pi += 128) {
                unsigned long long dxp = dadd2(sx2[pi], nqx);
                unsigned long long dyp = dadd2(sy2[pi], nqy);
                unsigned long long dzp = dadd2(sz2[pi], nqz);
                unsigned long long dp = dmul2(dxp, dxp);
                dp = dfmar2(dyp, dyp, dp);
                dp = dfmar2(dzp, dzp, dp);     // dz*dz + (dy*dy + dx*dx), per-lane IEEE
                float d0, d1;
                unpack2(dp, d0, d1);
                int c0 = base + 2*pi;
                unsigned bal = __ballot_sync(0xffffffffu, fminf(d0, d1) < tau);
                if (bal) insert2(bal, d0, d1, c0, ld, li, tau, lane);
            }
        }
        // publish sorted quarter-lists as lex (d_bits, idx) keys
        if (lane < 17)
            mkeys[q][quarter][lane] =
                ((unsigned long long)__float_as_uint(ld) << 32) | (unsigned)li;
        __syncthreads();

        if (quarter == 0) {
            // exact 4-way merge: top-17 of the 68 unique keys
            unsigned long long k0 = (lane < 17) ? mkeys[q][0][lane] : ~0ull;
            unsigned long long k1 = (lane < 17) ? mkeys[q][1][lane] : ~0ull;
            unsigned long long k2 = (lane < 17) ? mkeys[q][2][lane] : ~0ull;
            unsigned long long k3 = (lane < 17) ? mkeys[q][3][lane] : ~0ull;
            unsigned long long mykey = ~0ull;
            for (int j = 0; j < 17; j++) {
                unsigned long long la = (k0 < k1) ? k0 : k1;
                unsigned long long lb = (k2 < k3) ? k2 : k3;
                unsigned long long local = (la < lb) ? la : lb;
                unsigned long long mv = local;
                #pragma unroll
                for (int off = 16; off; off >>= 1) {
                    unsigned long long o = __shfl_xor_sync(0xffffffffu, mv, off);
                    mv = (o < mv) ? o : mv;
                }
                if (local == mv) {
                    if (k0 == mv) k0 = ~0ull;
                    else if (k1 == mv) k1 = ~0ull;
                    else if (k2 == mv) k2 = ~0ull;
                    else if (k3 == mv) k3 = ~0ull;
                }
                if (lane == j) mykey = mv;
            }
            // entry 0 = minimum (self); neighbors = entries 1..16
            if (lane >= 1 && lane < 17)
                sknn[q][lane - 1] = (int)(unsigned)(mykey & 0xFFFFFFFFull);
            __syncwarp();

            // logits + gumbel argmax
            const float* Q = g_Qf + ((size_t)b*NN + qidx) * NC;
            float qv0 = Q[lane], qv1 = Q[lane+32], qv2 = Q[lane+64], qv3 = Q[lane+96];
            float pk[16];
            #pragma unroll
            for (int k = 0; k < 16; k++) {
                const float* gr = Gf + (size_t)sknn[q][k] * NC;
                pk[k] = qv0*gr[lane] + qv1*gr[lane+32] + qv2*gr[lane+64] + qv3*gr[lane+96];
            }
            #pragma unroll
            for (int k = 0; k < 16; k++) {
                #pragma unroll
                for (int off = 16; off; off >>= 1)
                    pk[k] += __shfl_xor_sync(0xffffffffu, pk[k], off);
            }
            const float* gm = gumbel + ((((size_t)t*(NL-1) + l)*NB + b)*NM + m) * NK;
            float best = -CUDART_INF_F; int bk = 0;
            #pragma unroll
            for (int k = 0; k < 16; k++) {
                float s = pk[k] / 11.313708498984761f + gm[k];   // /sqrt(128)
                if (s > best) { best = s; bk = k; }
            }
            int nidx = sknn[q][bk];
            if (lane == 0) snext[q] = nidx;
            const float* fr = g_feats + ((size_t)b*NN + nidx) * NC;
            float* wr = g_wsel + ((size_t)gw * NL + (l + 1)) * NC;
            #pragma unroll
            for (int r = 0; r < 4; r++) wr[lane + 32*r] = fr[lane + 32*r];
        }
        __syncthreads();
        qidx = snext[q];
    }
}

// ---------------- route + predict: 4 seqs/block, 128 thr, dynamic smem ------
// buffers: [l2][ch][4] floats (two f32x2 seq-pairs per channel).
#define RSEQ 4
#define RTPB 128
#define RBUF (6*128*RSEQ)
#define RSMEM ((5*RBUF + RSEQ*4*36) * 4)

__device__ __forceinline__ void mm4(const float* in, const float* __restrict__ W,
                                    const float* __restrict__ bias, float* out,
                                    int c, bool doRelu) {
    unsigned long long acc[6][2];
    unsigned long long bb = packdup(bias[c]);
    #pragma unroll
    for (int l2 = 0; l2 < 6; l2++) { acc[l2][0] = bb; acc[l2][1] = bb; }
    const float4* wr = (const float4*)(W + (size_t)c * 128);
    const unsigned long long* inu = (const unsigned long long*)in;
    for (int j4 = 0; j4 < 32; j4++) {
        float4 w = __ldg(&wr[j4]);
        unsigned long long w0 = packdup(w.x), w1 = packdup(w.y);
        unsigned long long w2 = packdup(w.z), w3 = packdup(w.w);
        #pragma unroll
        for (int l2 = 0; l2 < 6; l2++) {
            const unsigned long long* r = inu + (size_t)(l2*128 + 4*j4)*2;
            dfma2(acc[l2][0], r[0], w0); dfma2(acc[l2][1], r[1], w0);
            dfma2(acc[l2][0], r[2], w1); dfma2(acc[l2][1], r[3], w1);
            dfma2(acc[l2][0], r[4], w2); dfma2(acc[l2][1], r[5], w2);
            dfma2(acc[l2][0], r[6], w3); dfma2(acc[l2][1], r[7], w3);
        }
    }
    #pragma unroll
    for (int l2 = 0; l2 < 6; l2++) {
        #pragma unroll
        for (int pp = 0; pp < 2; pp++) {
            float v0, v1;
            unpack2(acc[l2][pp], v0, v1);
            if (doRelu) { v0 = fmaxf(v0, 0.f); v1 = fmaxf(v1, 0.f); }
            out[(l2*128 + c)*4 + 2*pp + 0] = v0;
            out[(l2*128 + c)*4 + 2*pp + 1] = v1;
        }
    }
}

__global__ __launch_bounds__(RTPB)
void route_kernel(const float* __restrict__ w_in, const float* __restrict__ b_in,
                  const float* __restrict__ w_out, const float* __restrict__ b_out,
                  const float* __restrict__ rt_w1, const float* __restrict__ rt_b1,
                  const float* __restrict__ rt_w2, const float* __restrict__ rt_b2,
                  const float* __restrict__ pw1, const float* __restrict__ pb1,
                  const float* __restrict__ pw2, const float* __restrict__ pb2,
                  int curBuf, int prevBuf) {
    extern __shared__ float sdyn[];
    float* xin = sdyn;
    float* pin = sdyn + RBUF;
    float* qs  = sdyn + 2*RBUF;
    float* ks  = sdyn + 3*RBUF;
    float* vs  = sdyn + 4*RBUF;
    float* sc  = sdyn + 5*RBUF;   // [s][h][lq][lk]
    int tid = threadIdx.x;        // 128 threads, c = tid
    size_t seq0 = (size_t)blockIdx.x * RSEQ;
    const float* curr = g_wsel;
    const float* prev = (prevBuf < 0) ? g_wsel : g_rout[prevBuf];
    for (int i = tid; i < RBUF; i += RTPB) {
        int s = i & 3, r = i >> 2;
        xin[i] = curr[(seq0 + s)*768 + r];
        pin[i] = prev[(seq0 + s)*768 + r];
    }
    __syncthreads();
    mm4(xin, w_in,            b_in,        qs, tid, false);
    mm4(pin, w_in + 128*128,  b_in + 128,  ks, tid, false);
    mm4(pin, w_in + 256*128,  b_in + 256,  vs, tid, false);
    __syncthreads();
    int warp = tid >> 5, lane = tid & 31;
    for (int pp = warp; pp < 16; pp += 4) {
        int s = pp >> 2, h = pp & 3;
        for (int e = lane; e < 36; e += 32) {
            int lq = e / 6, lk = e % 6;
            float d = 0.f;
            #pragma unroll
            for (int dd = 0; dd < 32; dd++)
                d += qs[(lq*128 + h*32 + dd)*4 + s] * ks[(lk*128 + h*32 + dd)*4 + s];
            sc[((s*4 + h)*6 + lq)*6 + lk] = d / 5.656854249492381f;
        }
        __syncwarp();
        if (lane < 6) {
            float* row = &sc[((s*4 + h)*6 + lane)*6];
            float mx = -CUDART_INF_F;
            #pragma unroll
            for (int j = 0; j < 6; j++) mx = fmaxf(mx, row[j]);
            float exv[6]; float sum = 0.f;
            #pragma unroll
            for (int j = 0; j < 6; j++) { exv[j] = expf(row[j] - mx); sum += exv[j]; }
            #pragma unroll
            for (int j = 0; j < 6; j++) row[j] = exv[j] / sum;
        }
        __syncwarp();
        for (int lq = 0; lq < 6; lq++) {
            float o = 0.f;
            #pragma unroll
            for (int j = 0; j < 6; j++)
                o += sc[((s*4 + h)*6 + lq)*6 + j] * vs[(j*128 + h*32 + lane)*4 + s];
            xin[(lq*128 + h*32 + lane)*4 + s] = o;
        }
    }
    __syncthreads();
    mm4(xin, w_out, b_out, pin, tid, false);
    __syncthreads();
    mm4(pin, rt_w1, rt_b1, qs, tid, true);
    __syncthreads();
    mm4(qs, rt_w2, rt_b2, ks, tid, false);
    __syncthreads();
    float* dst = g_rout[curBuf] + seq0*768;
    for (int i = tid; i < RBUF; i += RTPB) {
        int s = i & 3, r = i >> 2;
        dst[(size_t)s*768 + r] = ks[i];
    }
    // ---- fused predict head ----
    float* xv = qs;    // [4][256]
    float* hv = vs;    // [4][64]
    for (int i = tid; i < 4*128; i += RTPB) {
        int s = i >> 7, ch = i & 127;
        float cent = ks[(0*128 + ch)*4 + s];
        float sum = 0.f;
        #pragma unroll
        for (int l2 = 1; l2 < 6; l2++) sum += (ks[(l2*128 + ch)*4 + s] - cent);
        xv[s*256 + ch]       = sum * (1.0f / 5.0f);
        xv[s*256 + 128 + ch] = cent;
    }
    __syncthreads();
    for (int i = tid; i < 4*64; i += RTPB) {
        int s = i >> 6, j = i & 63;
        float acc = pb1[j];
        const float4* wr = (const float4*)(pw1 + (size_t)j * 256);
        const float4* xr = (const float4*)(xv + s*256);
        #pragma unroll 8
        for (int j4 = 0; j4 < 64; j4++) {
            float4 wv = wr[j4];
            float4 x4 = xr[j4];
            acc += wv.x*x4.x + wv.y*x4.y + wv.z*x4.z + wv.w*x4.w;
        }
        hv[s*64 + j] = fmaxf(acc, 0.f);
    }
    __syncthreads();
    if (tid < 12) {
        int s = tid / 3, o = tid % 3;
        float acc = pb2[o];
        const float* wr = pw2 + o * 64;
        const float* hh = hv + s*64;
        #pragma unroll 8
        for (int j = 0; j < 64; j++) acc += wr[j] * hh[j];
        g_disp[(seq0 + s)*3 + o] = tanhf(acc);
    }
}

// ---------------- deterministic duplicate-aware scatter-add -----------------
__global__ void scatter_kernel(const int* __restrict__ start) {
    int gid = blockIdx.x * blockDim.x + threadIdx.x;
    if (gid >= NB*NM) return;
    int b = gid >> 9, m = gid & 511;
    int n = start[gid];
    const int* sb = start + b * NM;
    for (int j = 0; j < m; j++) if (sb[j] == n) return;
    float sx = 0.f, sy = 0.f, sz = 0.f;
    for (int j = m; j < NM; j++) {
        if (sb[j] == n) {
            const float* d = g_disp + (size_t)(b*NM + j) * 3;
            sx += d[0]; sy += d[1]; sz += d[2];
        }
    }
    float* p = g_pos4 + ((size_t)b*NN + n) * 4;
    p[0] += sx; p[1] += sy; p[2] += sz;
}

__global__ void finalize_kernel(float* __restrict__ out) {
    int i = blockIdx.x * blockDim.x + threadIdx.x;
    if (i < NB*NN) {
        out[i*3+0] = g_pos4[(size_t)i*4+0];
        out[i*3+1] = g_pos4[(size_t)i*4+1];
        out[i*3+2] = g_pos4[(size_t)i*4+2];
    }
}

// ---------------- host driver ----------------------------------------------
extern "C" void kernel_launch(void* const* d_in, const int* in_sizes, int n_in,
                              void* d_out, int out_size) {
    (void)in_sizes; (void)n_in; (void)out_size;
    const float* xyz      = (const float*)d_in[0];
    const int*   start    = (const int*)  d_in[1];
    const float* gumbel   = (const float*)d_in[2];
    const float* enc_w1   = (const float*)d_in[3];
    const float* enc_b1   = (const float*)d_in[4];
    const float* enc_w2   = (const float*)d_in[5];
    const float* enc_b2   = (const float*)d_in[6];
    const float* beta_w   = (const float*)d_in[7];
    const float* beta_b   = (const float*)d_in[8];
    const float* gamma_w  = (const float*)d_in[9];
    const float* gamma_b  = (const float*)d_in[10];
    const float* attn_w_in  = (const float*)d_in[11];
    const float* attn_b_in  = (const float*)d_in[12];
    const float* attn_w_out = (const float*)d_in[13];
    const float* attn_b_out = (const float*)d_in[14];
    const float* rt_w1    = (const float*)d_in[15];
    const float* rt_b1    = (const float*)d_in[16];
    const float* rt_w2    = (const float*)d_in[17];
    const float* rt_b2    = (const float*)d_in[18];
    const float* pred_w1  = (const float*)d_in[19];
    const float* pred_b1  = (const float*)d_in[20];
    const float* pred_w2  = (const float*)d_in[21];
    const float* pred_b2  = (const float*)d_in[22];

    cudaFuncSetAttribute(route_kernel,
                         cudaFuncAttributeMaxDynamicSharedMemorySize, RSMEM);

    init_pos_kernel<<<(NB*NN + 127)/128, 128>>>(xyz);
    encode_kernel<<<NB*NN/4, 128>>>(xyz, enc_w1, enc_b1, enc_w2, enc_b2);
    proj_kernel<<<NB*NN/16, 128>>>(beta_w, beta_b, gamma_w, gamma_b);

    for (int t = 0; t < NSTEPS; t++) {
        int cur = t & 1;
        int prv = (t == 0) ? -1 : (1 - cur);
        knn_step_kernel<<<NB*NM/KQB, KTPB>>>(start, gumbel, t);
        route_kernel<<<NB*NM/RSEQ, RTPB, RSMEM>>>(
            attn_w_in, attn_b_in, attn_w_out, attn_b_out,
            rt_w1, rt_b1, rt_w2, rt_b2,
            pred_w1, pred_b1, pred_w2, pred_b2, cur, prv);
        scatter_kernel<<<(NB*NM + 127)/128, 128>>>(start);
    }
    finalize_kernel<<<(NB*NN + 127)/128, 128>>>((float*)d_out);
}

// round 13
// speedup vs baseline: 1.8141x; 1.8141x over previous
#include <cuda_runtime.h>
#include <math_constants.h>

#define NB 4
#define NN 16384
#define NM 512
#define NC 128
#define NK 16
#define NL 6
#define NSTEPS 5

// ---------------- scratch (device globals: no allocations allowed) ----------
__device__ float g_feats[NB*NN*NC];
__device__ float g_Qf[NB*NN*NC];
__device__ float g_Gf[NB*NN*NC];
__device__ __align__(16) float g_pos4[NB*NN*4];
__device__ float g_wsel[NB*NM*NL*NC];
__device__ float g_rout[2][NB*NM*NL*NC];
__device__ float g_disp[NB*NM*3];

// ---------------- f32x2 packed helpers --------------------------------------
__device__ __forceinline__ void dfma2(unsigned long long& d,
                                      unsigned long long a,
                                      unsigned long long b) {
    asm("fma.rn.f32x2 %0, %1, %2, %0;" : "+l"(d) : "l"(a), "l"(b));
}
__device__ __forceinline__ unsigned long long dadd2(unsigned long long a,
                                                    unsigned long long b) {
    unsigned long long r;
    asm("add.rn.f32x2 %0, %1, %2;" : "=l"(r) : "l"(a), "l"(b));
    return r;
}
__device__ __forceinline__ unsigned long long dmul2(unsigned long long a,
                                                    unsigned long long b) {
    unsigned long long r;
    asm("mul.rn.f32x2 %0, %1, %2;" : "=l"(r) : "l"(a), "l"(b));
    return r;
}
__device__ __forceinline__ unsigned long long dfmar2(unsigned long long a,
                                                     unsigned long long b,
                                                     unsigned long long c) {
    unsigned long long r;
    asm("fma.rn.f32x2 %0, %1, %2, %3;" : "=l"(r) : "l"(a), "l"(b), "l"(c));
    return r;
}
__device__ __forceinline__ unsigned long long packdup(float w) {
    unsigned long long r;
    asm("mov.b64 %0, {%1, %1};" : "=l"(r) : "f"(w));
    return r;
}
__device__ __forceinline__ void unpack2(unsigned long long a, float& lo, float& hi) {
    asm("mov.b64 {%0, %1}, %2;" : "=f"(lo), "=f"(hi) : "l"(a));
}

// ---------------- fused init + encoder --------------------------------------
// 4 points / block: write padded positions AND encoder features.
__global__ void init_encode_kernel(const float* __restrict__ xyz,
                                   const float* __restrict__ w1, const float* __restrict__ b1,
                                   const float* __restrict__ w2, const float* __restrict__ b2) {
    __shared__ float h[4][64];
    int tid = threadIdx.x;
    int p0 = blockIdx.x * 4;
    if (tid < 4) {
        const float* x = xyz + (size_t)(p0 + tid) * 3;
        *(float4*)&g_pos4[(size_t)(p0 + tid)*4] = make_float4(x[0], x[1], x[2], 0.f);
    }
    for (int i = tid; i < 4*64; i += 128) {
        int pt = i >> 6, j = i & 63;
        const float* x = xyz + (size_t)(p0 + pt) * 3;
        float v = b1[j] + w1[j*3+0]*x[0] + w1[j*3+1]*x[1] + w1[j*3+2]*x[2];
        h[pt][j] = fmaxf(v, 0.f);
    }
    __syncthreads();
    float acc[4];
    #pragma unroll
    for (int p = 0; p < 4; p++) acc[p] = b2[tid];
    const float4* wr = (const float4*)(w2 + (size_t)tid * 64);
    #pragma unroll
    for (int j4 = 0; j4 < 16; j4++) {
        float4 w = wr[j4];
        #pragma unroll
        for (int p = 0; p < 4; p++) {
            float4 hv = *(const float4*)&h[p][4*j4];
            acc[p] += w.x*hv.x + w.y*hv.y + w.z*hv.z + w.w*hv.w;
        }
    }
    #pragma unroll
    for (int p = 0; p < 4; p++)
        g_feats[(size_t)(p0 + p) * NC + tid] = acc[p];
}

// ---------------- beta/gamma projections (f32x2 point-pairs) ----------------
__global__ void proj_kernel(const float* __restrict__ bw, const float* __restrict__ bb,
                            const float* __restrict__ gw, const float* __restrict__ gb) {
    __shared__ __align__(8) float xs[128*16];      // xs[ch*16 + p]
    int c = threadIdx.x;                           // 128 threads
    size_t base = (size_t)blockIdx.x * 16 * 128;
    for (int i = c; i < 16*128; i += 128) {
        int p = i >> 7, ch = i & 127;
        xs[ch*16 + p] = g_feats[base + i];
    }
    __syncthreads();
    unsigned long long accQ[8], accG[8];
    unsigned long long bq = packdup(bb[c]), bg = packdup(gb[c]);
    #pragma unroll
    for (int p = 0; p < 8; p++) { accQ[p] = bq; accG[p] = bg; }
    const float4* wq = (const float4*)(bw + (size_t)c * 128);
    const float4* wg = (const float4*)(gw + (size_t)c * 128);
    for (int j4 = 0; j4 < 32; j4++) {
        float4 a = wq[j4];
        float4 g = wg[j4];
        float aa[4] = {a.x, a.y, a.z, a.w};
        float gg2[4] = {g.x, g.y, g.z, g.w};
        #pragma unroll
        for (int jj = 0; jj < 4; jj++) {
            int ch = 4*j4 + jj;
            unsigned long long wa = packdup(aa[jj]);
            unsigned long long wgv = packdup(gg2[jj]);
            const unsigned long long* x2 = (const unsigned long long*)&xs[ch*16];
            #pragma unroll
            for (int p = 0; p < 8; p++) {
                dfma2(accQ[p], x2[p], wa);
                dfma2(accG[p], x2[p], wgv);
            }
        }
    }
    #pragma unroll
    for (int p = 0; p < 8; p++) {
        float q0, q1, g0, g1;
        unpack2(accQ[p], q0, q1);
        unpack2(accG[p], g0, g1);
        g_Qf[base + (size_t)(2*p)*128 + c]   = q0;
        g_Qf[base + (size_t)(2*p+1)*128 + c] = q1;
        g_Gf[base + (size_t)(2*p)*128 + c]   = g0;
        g_Gf[base + (size_t)(2*p+1)*128 + c] = g1;
    }
}

// ---------------- KNN: warp-distributed sorted top-17 insert (R10-exact) ----
__device__ __forceinline__ void kinsert(unsigned bal, float d, int ci,
                                        float& ld, int& li, float& tau, int lane) {
    do {
        int src = __ffs(bal) - 1; bal &= bal - 1;
        float dc = __shfl_sync(0xffffffffu, d, src);
        int   ic = __shfl_sync(0xffffffffu, ci, src);
        float pd = __shfl_up_sync(0xffffffffu, ld, 1);
        int   pi = __shfl_up_sync(0xffffffffu, li, 1);
        unsigned lt = __ballot_sync(0xffffffffu,
                (ld < dc) || ((ld == dc) && (li < ic))) & 0x1FFFFu;
        int pn = __popc(lt);
        if (lane < 17) {
            if (lane == pn)      { ld = dc; li = ic; }
            else if (lane > pn)  { ld = pd; li = pi; }
        }
    } while (bal);
    tau = __shfl_sync(0xffffffffu, ld, 16);
}

// ---------------- fused per-step selector, positions resident in smem ------
// 128 blocks x 512 threads. Each block stages its batch's FULL 16384-point
// SoA into 192KB dynamic smem ONCE, then each of 16 warps runs one query
// through all 5 levels (scan + top-17 + logits + gumbel argmax) with zero
// further block barriers. Scan math identical to R10 (packed f32x2, per-lane
// IEEE), selection identical (lex (d, idx) sorted top-17).
#define KTPB 512
#define KQPB 16
#define KNN_SMEM (3*NN*4)

__global__ __launch_bounds__(KTPB)
void knn_step_kernel(const int* __restrict__ start,
                     const float* __restrict__ gumbel, int t) {
    extern __shared__ __align__(8) float sm[];
    float* sx = sm;
    float* sy = sm + NN;
    float* sz = sm + 2*NN;
    int tid = threadIdx.x, warp = tid >> 5, lane = tid & 31;
    int b = blockIdx.x / (NM/KQPB);             // 32 blocks per batch
    int m = (blockIdx.x % (NM/KQPB)) * KQPB + warp;
    int gw = b*NM + m;
    int qidx = start[gw];
    const float4* pos = (const float4*)(g_pos4 + (size_t)b*NN*4);
    const float* Gf = g_Gf + (size_t)b*NN*NC;

    // stage the whole batch once
    for (int i = tid; i < NN; i += KTPB) {
        float4 p = pos[i];
        sx[i] = p.x; sy[i] = p.y; sz[i] = p.z;
    }
    {   // walk[0] = feats[start]
        const float* fr = g_feats + ((size_t)b*NN + qidx) * NC;
        float* wr = g_wsel + (size_t)gw * NL * NC;
        #pragma unroll
        for (int r = 0; r < 4; r++) wr[lane + 32*r] = fr[lane + 32*r];
    }
    __syncthreads();

    const unsigned long long* sx2 = (const unsigned long long*)sx;
    const unsigned long long* sy2 = (const unsigned long long*)sy;
    const unsigned long long* sz2 = (const unsigned long long*)sz;

    for (int l = 0; l < NL-1; l++) {
        float qx = sx[qidx], qy = sy[qidx], qz = sz[qidx];
        unsigned long long nqx = packdup(-qx);
        unsigned long long nqy = packdup(-qy);
        unsigned long long nqz = packdup(-qz);
        float ld = CUDART_INF_F;
        int   li = 0x7FFFFFFF;
        float tau = CUDART_INF_F;

        for (int pi = lane; pi < NN/2; pi += 32) {
            unsigned long long dxp = dadd2(sx2[pi], nqx);
            unsigned long long dyp = dadd2(sy2[pi], nqy);
            unsigned long long dzp = dadd2(sz2[pi], nqz);
            unsigned long long dp = dmul2(dxp, dxp);
            dp = dfmar2(dyp, dyp, dp);
            dp = dfmar2(dzp, dzp, dp);       // dz*dz + (dy*dy + dx*dx), per-lane IEEE
            float d0, d1;
            unpack2(dp, d0, d1);
            int c0 = 2*pi;
            unsigned bal0 = __ballot_sync(0xffffffffu, d0 < tau);
            if (bal0) kinsert(bal0, d0, c0, ld, li, tau, lane);
            unsigned bal1 = __ballot_sync(0xffffffffu, d1 < tau);
            if (bal1) kinsert(bal1, d1, c0 + 1, ld, li, tau, lane);
        }

        // lanes 0..16 = sorted top-17 (lex (d, idx)); lane0 = self
        int nb = __shfl_sync(0xffffffffu, li, lane < 31 ? lane + 1 : 31);
        // nb for lanes 0..15 = neighbors 1..16
        // logits + gumbel argmax (neighbor k lives in lane k+1's li)
        const float* Q = g_Qf + ((size_t)b*NN + qidx) * NC;
        float qv0 = Q[lane], qv1 = Q[lane+32], qv2 = Q[lane+64], qv3 = Q[lane+96];
        float pk[16];
        #pragma unroll
        for (int k = 0; k < 16; k++) {
            int nk = __shfl_sync(0xffffffffu, nb, k);   // = li of lane k+1
            const float* gr = Gf + (size_t)nk * NC;
            pk[k] = qv0*gr[lane] + qv1*gr[lane+32] + qv2*gr[lane+64] + qv3*gr[lane+96];
        }
        #pragma unroll
        for (int k = 0; k < 16; k++) {
            #pragma unroll
            for (int off = 16; off; off >>= 1)
                pk[k] += __shfl_xor_sync(0xffffffffu, pk[k], off);
        }
        const float* gm = gumbel + ((((size_t)t*(NL-1) + l)*NB + b)*NM + m) * NK;
        float best = -CUDART_INF_F; int bk = 0;
        #pragma unroll
        for (int k = 0; k < 16; k++) {
            float s = pk[k] / 11.313708498984761f + gm[k];   // /sqrt(128)
            if (s > best) { best = s; bk = k; }
        }
        qidx = __shfl_sync(0xffffffffu, li, bk + 1);
        const float* fr = g_feats + ((size_t)b*NN + qidx) * NC;
        float* wr = g_wsel + ((size_t)gw * NL + (l + 1)) * NC;
        #pragma unroll
        for (int r = 0; r < 4; r++) wr[lane + 32*r] = fr[lane + 32*r];
    }
}

// ---------------- route + predict fused (R10-exact: 64 thr, 2 ch/thread) ---
__device__ __forceinline__ void mm64(const float (*in)[128][2],
                                     const float* __restrict__ W,
                                     const float* __restrict__ bias,
                                     float (*out)[128][2],
                                     int tid, bool doRelu) {
    unsigned long long acc0[6], acc1[6];
    unsigned long long b0 = packdup(bias[tid]), b1 = packdup(bias[tid + 64]);
    #pragma unroll
    for (int i = 0; i < 6; i++) { acc0[i] = b0; acc1[i] = b1; }
    const float4* wr0 = (const float4*)(W + (size_t)tid * 128);
    const float4* wr1 = (const float4*)(W + (size_t)(tid + 64) * 128);
    const unsigned long long* inu = (const unsigned long long*)in;
    for (int j4 = 0; j4 < 32; j4++) {
        float4 wa = __ldg(&wr0[j4]);
        float4 wb = __ldg(&wr1[j4]);
        unsigned long long a0 = packdup(wa.x), a1 = packdup(wa.y);
        unsigned long long a2 = packdup(wa.z), a3 = packdup(wa.w);
        unsigned long long c0 = packdup(wb.x), c1 = packdup(wb.y);
        unsigned long long c2 = packdup(wb.z), c3 = packdup(wb.w);
        #pragma unroll
        for (int l2 = 0; l2 < 6; l2++) {
            const unsigned long long* row = inu + l2*128 + 4*j4;
            unsigned long long r0 = row[0], r1 = row[1], r2 = row[2], r3 = row[3];
            dfma2(acc0[l2], r0, a0); dfma2(acc1[l2], r0, c0);
            dfma2(acc0[l2], r1, a1); dfma2(acc1[l2], r1, c1);
            dfma2(acc0[l2], r2, a2); dfma2(acc1[l2], r2, c2);
            dfma2(acc0[l2], r3, a3); dfma2(acc1[l2], r3, c3);
        }
    }
    #pragma unroll
    for (int l2 = 0; l2 < 6; l2++) {
        float v0, v1, u0, u1;
        unpack2(acc0[l2], v0, v1);
        unpack2(acc1[l2], u0, u1);
        if (doRelu) {
            v0 = fmaxf(v0, 0.f); v1 = fmaxf(v1, 0.f);
            u0 = fmaxf(u0, 0.f); u1 = fmaxf(u1, 0.f);
        }
        out[l2][tid][0] = v0;      out[l2][tid][1] = v1;
        out[l2][tid+64][0] = u0;   out[l2][tid+64][1] = u1;
    }
}

__global__ void route_kernel(const float* __restrict__ w_in, const float* __restrict__ b_in,
                             const float* __restrict__ w_out, const float* __restrict__ b_out,
                             const float* __restrict__ rt_w1, const float* __restrict__ rt_b1,
                             const float* __restrict__ rt_w2, const float* __restrict__ rt_b2,
                             const float* __restrict__ pw1, const float* __restrict__ pb1,
                             const float* __restrict__ pw2, const float* __restrict__ pb2,
                             int curBuf, int prevBuf) {
    __shared__ __align__(16) float xin[6][128][2];
    __shared__ __align__(16) float pin[6][128][2];
    __shared__ __align__(16) float qs[6][128][2];
    __shared__ __align__(16) float ks[6][128][2];
    __shared__ __align__(16) float vs[6][128][2];
    __shared__ float sc[2][4][6][6];
    int tid = threadIdx.x;                      // 64 threads
    size_t seq0 = (size_t)blockIdx.x * 2;
    const float* curr = g_wsel;
    const float* prev = (prevBuf < 0) ? g_wsel : g_rout[prevBuf];
    for (int i = tid; i < 2*6*128; i += 64) {
        int s = i / 768, r = i % 768;
        ((float*)xin)[r*2 + s] = curr[(seq0 + s)*768 + r];
        ((float*)pin)[r*2 + s] = prev[(seq0 + s)*768 + r];
    }
    __syncthreads();
    mm64(xin, w_in,            b_in,        qs, tid, false);
    mm64(pin, w_in + 128*128,  b_in + 128,  ks, tid, false);
    mm64(pin, w_in + 256*128,  b_in + 256,  vs, tid, false);
    __syncthreads();
    int warp = tid >> 5, lane = tid & 31;
    for (int pp = warp; pp < 8; pp += 2) {
        int s = pp >> 2, h = pp & 3;
        for (int e = lane; e < 36; e += 32) {
            int lq = e / 6, lk = e % 6;
            float d = 0.f;
            #pragma unroll
            for (int dd = 0; dd < 32; dd++)
                d += qs[lq][h*32 + dd][s] * ks[lk][h*32 + dd][s];
            sc[s][h][lq][lk] = d / 5.656854249492381f;
        }
        __syncwarp();
        if (lane < 6) {
            float mx = -CUDART_INF_F;
            #pragma unroll
            for (int j = 0; j < 6; j++) mx = fmaxf(mx, sc[s][h][lane][j]);
            float ex[6]; float sum = 0.f;
            #pragma unroll
            for (int j = 0; j < 6; j++) { ex[j] = expf(sc[s][h][lane][j] - mx); sum += ex[j]; }
            #pragma unroll
            for (int j = 0; j < 6; j++) sc[s][h][lane][j] = ex[j] / sum;
        }
        __syncwarp();
        for (int lq = 0; lq < 6; lq++) {
            float o = 0.f;
            #pragma unroll
            for (int j = 0; j < 6; j++) o += sc[s][h][lq][j] * vs[j][h*32 + lane][s];
            xin[lq][h*32 + lane][s] = o;
        }
    }
    __syncthreads();
    mm64(xin, w_out, b_out, pin, tid, false);
    __syncthreads();
    mm64(pin, rt_w1, rt_b1, qs, tid, true);
    __syncthreads();
    mm64(qs, rt_w2, rt_b2, ks, tid, false);
    __syncthreads();
    float* dst = g_rout[curBuf] + seq0*768;
    for (int i = tid; i < 2*6*128; i += 64) {
        int s = i / 768, r = i % 768;
        dst[(size_t)s*768 + r] = ((float*)ks)[r*2 + s];
    }
    // ---- fused predict head ----
    float* xv = (float*)qs;    // x: [2][256]
    float* hv = (float*)vs;    // h: [2][64]
    for (int c = tid; c < 128; c += 64) {
        #pragma unroll
        for (int s = 0; s < 2; s++) {
            float cent = ks[0][c][s];
            float sum = 0.f;
            #pragma unroll
            for (int l2 = 1; l2 < 6; l2++) sum += (ks[l2][c][s] - cent);
            xv[s*256 + c]       = sum * (1.0f / 5.0f);
            xv[s*256 + 128 + c] = cent;
        }
    }
    __syncthreads();
    #pragma unroll
    for (int s = 0; s < 2; s++) {
        int j = tid;
        float acc = pb1[j];
        const float4* wr = (const float4*)(pw1 + (size_t)j * 256);
        const float4* xr = (const float4*)(xv + s*256);
        #pragma unroll 8
        for (int j4 = 0; j4 < 64; j4++) {
            float4 wv = wr[j4];
            float4 x4 = xr[j4];
            acc += wv.x*x4.x + wv.y*x4.y + wv.z*x4.z + wv.w*x4.w;
        }
        hv[s*64 + j] = fmaxf(acc, 0.f);
    }
    __syncthreads();
    if (tid < 6) {
        int s = tid / 3, o = tid % 3;
        float acc = pb2[o];
        const float* wr = pw2 + o * 64;
        const float* hh = hv + s*64;
        #pragma unroll 8
        for (int j = 0; j < 64; j++) acc += wr[j] * hh[j];
        g_disp[(seq0 + s)*3 + o] = tanhf(acc);
    }
}

// ---------------- deterministic duplicate-aware scatter-add -----------------
__global__ void scatter_kernel(const int* __restrict__ start) {
    int gid = blockIdx.x * blockDim.x + threadIdx.x;
    if (gid >= NB*NM) return;
    int b = gid >> 9, m = gid & 511;
    int n = start[gid];
    const int* sb = start + b * NM;
    for (int j = 0; j < m; j++) if (sb[j] == n) return;
    float sx = 0.f, sy = 0.f, sz = 0.f;
    for (int j = m; j < NM; j++) {
        if (sb[j] == n) {
            const float* d = g_disp + (size_t)(b*NM + j) * 3;
            sx += d[0]; sy += d[1]; sz += d[2];
        }
    }
    float* p = g_pos4 + ((size_t)b*NN + n) * 4;
    p[0] += sx; p[1] += sy; p[2] += sz;
}

__global__ void finalize_kernel(float* __restrict__ out) {
    int i = blockIdx.x * blockDim.x + threadIdx.x;
    if (i < NB*NN) {
        out[i*3+0] = g_pos4[(size_t)i*4+0];
        out[i*3+1] = g_pos4[(size_t)i*4+1];
        out[i*3+2] = g_pos4[(size_t)i*4+2];
    }
}

// ---------------- host driver ----------------------------------------------
extern "C" void kernel_launch(void* const* d_in, const int* in_sizes, int n_in,
                              void* d_out, int out_size) {
    (void)in_sizes; (void)n_in; (void)out_size;
    const float* xyz      = (const float*)d_in[0];
    const int*   start    = (const int*)  d_in[1];
    const float* gumbel   = (const float*)d_in[2];
    const float* enc_w1   = (const float*)d_in[3];
    const float* enc_b1   = (const float*)d_in[4];
    const float* enc_w2   = (const float*)d_in[5];
    const float* enc_b2   = (const float*)d_in[6];
    const float* beta_w   = (const float*)d_in[7];
    const float* beta_b   = (const float*)d_in[8];
    const float* gamma_w  = (const float*)d_in[9];
    const float* gamma_b  = (const float*)d_in[10];
    const float* attn_w_in  = (const float*)d_in[11];
    const float* attn_b_in  = (const float*)d_in[12];
    const float* attn_w_out = (const float*)d_in[13];
    const float* attn_b_out = (const float*)d_in[14];
    const float* rt_w1    = (const float*)d_in[15];
    const float* rt_b1    = (const float*)d_in[16];
    const float* rt_w2    = (const float*)d_in[17];
    const float* rt_b2    = (const float*)d_in[18];
    const float* pred_w1  = (const float*)d_in[19];
    const float* pred_b1  = (const float*)d_in[20];
    const float* pred_w2  = (const float*)d_in[21];
    const float* pred_b2  = (const float*)d_in[22];

    cudaFuncSetAttribute(knn_step_kernel,
                         cudaFuncAttributeMaxDynamicSharedMemorySize, KNN_SMEM);

    init_encode_kernel<<<NB*NN/4, 128>>>(xyz, enc_w1, enc_b1, enc_w2, enc_b2);
    proj_kernel<<<NB*NN/16, 128>>>(beta_w, beta_b, gamma_w, gamma_b);

    for (int t = 0; t < NSTEPS; t++) {
        int cur = t & 1;
        int prv = (t == 0) ? -1 : (1 - cur);
        knn_step_kernel<<<NB*NM/KQPB, KTPB, KNN_SMEM>>>(start, gumbel, t);
        route_kernel<<<NB*NM/2, 64>>>(attn_w_in, attn_b_in, attn_w_out, attn_b_out,
                                      rt_w1, rt_b1, rt_w2, rt_b2,
                                      pred_w1, pred_b1, pred_w2, pred_b2, cur, prv);
        scatter_kernel<<<(NB*NM + 127)/128, 128>>>(start);
    }
    finalize_kernel<<<(NB*NN + 127)/128, 128>>>((float*)d_out);
}